// round 3
// baseline (speedup 1.0000x reference)
#include <cuda_runtime.h>
#include <cuda_bf16.h>
#include <cstdint>
#include <math.h>

// Problem constants (fixed shapes for this problem)
#define PDIM   128              // n_proxy_sets
#define EDIM   32               // elements per proxy set
#define DDIM   64               // feature dim
#define PE     (PDIM*EDIM)      // 4096 flattened proxies
#define NCHUNK 64               // proxies per inner chunk (= 2 full p-groups)
#define NCHUNKS (PE/NCHUNK)     // 64
#define TILE_M 128              // x rows per tile (= SEG_LEN here)
#define XPITCH 72               // padded bf16 row pitch (conflict-free ldmatrix)
#define WPITCH 72
#define THREADS 256
#define MAXB   1024

// Scratch (no cudaMalloc allowed)
__device__ __nv_bfloat16 g_wbf[PE * DDIM];   // 512 KB, stays hot in L2
__device__ int g_segoff[MAXB];

// ---------------- helper kernels ----------------

__global__ void convw_kernel(const float* __restrict__ w, int n) {
    int i = blockIdx.x * blockDim.x + threadIdx.x;
    if (i < n) g_wbf[i] = __float2bfloat16(w[i]);
}

// exclusive prefix sum of segment lengths (B <= 1024, single block)
__global__ void scan_kernel(const int* __restrict__ index, int B) {
    __shared__ int s[MAXB];
    int t = threadIdx.x;
    int v = (t < B) ? index[t] : 0;
    s[t] = v;
    __syncthreads();
    for (int o = 1; o < MAXB; o <<= 1) {
        int add = (t >= o) ? s[t - o] : 0;
        __syncthreads();
        s[t] += add;
        __syncthreads();
    }
    if (t < B) g_segoff[t] = s[t] - v;
}

// ---------------- MMA primitives ----------------

__device__ __forceinline__ void ldsm_x4(uint32_t& r0, uint32_t& r1,
                                        uint32_t& r2, uint32_t& r3,
                                        const void* p) {
    uint32_t a = (uint32_t)__cvta_generic_to_shared(p);
    asm volatile("ldmatrix.sync.aligned.m8n8.x4.shared.b16 {%0,%1,%2,%3}, [%4];"
                 : "=r"(r0), "=r"(r1), "=r"(r2), "=r"(r3) : "r"(a));
}

__device__ __forceinline__ void mma_bf16(float* c, const uint32_t* a,
                                         uint32_t b0, uint32_t b1) {
    asm volatile(
        "mma.sync.aligned.m16n8k16.row.col.f32.bf16.bf16.f32 "
        "{%0,%1,%2,%3}, {%4,%5,%6,%7}, {%8,%9}, {%0,%1,%2,%3};"
        : "+f"(c[0]), "+f"(c[1]), "+f"(c[2]), "+f"(c[3])
        : "r"(a[0]), "r"(a[1]), "r"(a[2]), "r"(a[3]), "r"(b0), "r"(b1));
}

// ---------------- main kernel ----------------
// One CTA per segment. M=128 x-rows (bf16 in smem, A-frags pinned in regs),
// sweep 4096 proxies in chunks of 64 (8 n-tiles), fused max-over-e + row-sum
// epilogue in registers, smem atomic accumulate into pooled[P], then L2 norm.

__global__ __launch_bounds__(THREADS, 2)
void main_kernel(const float* __restrict__ x, const int* __restrict__ index,
                 float* __restrict__ out) {
    __shared__ __nv_bfloat16 xs[TILE_M * XPITCH];   // 18 KB
    __shared__ __nv_bfloat16 ws[NCHUNK * WPITCH];   // 9 KB
    __shared__ float pooled[PDIM];
    __shared__ float red[8];

    const int b    = blockIdx.x;
    const int tid  = threadIdx.x;
    const int lane = tid & 31;
    const int warp = tid >> 5;

    for (int i = tid; i < PDIM; i += THREADS) pooled[i] = 0.f;

    const int off = g_segoff[b];
    const int len = index[b];

    for (int tile = 0; tile * TILE_M < len; ++tile) {
        __syncthreads();   // pooled-init / previous-tile drain
        // ---- load + convert x tile (zero-pad ragged tail) ----
        {
            int row  = tid >> 1;
            int half = tid & 1;
            int rrem = len - tile * TILE_M;
            bool valid = row < rrem;
            const float* xr = x + ((size_t)(off + tile * TILE_M + row)) * DDIM + half * 32;
            __nv_bfloat162* dst = (__nv_bfloat162*)&xs[row * XPITCH + half * 32];
            #pragma unroll
            for (int j = 0; j < 8; ++j) {
                float4 v = valid ? __ldg((const float4*)xr + j)
                                 : make_float4(0.f, 0.f, 0.f, 0.f);
                dst[2 * j]     = __floats2bfloat162_rn(v.x, v.y);
                dst[2 * j + 1] = __floats2bfloat162_rn(v.z, v.w);
            }
        }
        __syncthreads();

        // ---- A fragments: 16 rows per warp, K=64 (4 k-steps), pinned in regs ----
        uint32_t afr[4][4];
        {
            const __nv_bfloat16* base =
                &xs[(warp * 16 + (lane & 15)) * XPITCH + (lane >> 4) * 8];
            #pragma unroll
            for (int k = 0; k < 4; ++k)
                ldsm_x4(afr[k][0], afr[k][1], afr[k][2], afr[k][3], base + k * 16);
        }

        // ---- register-prefetch chunk 0 proxy tile (64x64 bf16 = 8KB) ----
        uint4 w0, w1;
        {
            int u0 = tid, u1 = tid + 256;
            w0 = *((const uint4*)(g_wbf + (u0 >> 3) * DDIM) + (u0 & 7));
            w1 = *((const uint4*)(g_wbf + (u1 >> 3) * DDIM) + (u1 & 7));
        }

        for (int c = 0; c < NCHUNKS; ++c) {
            __syncthreads();   // everyone done reading ws of previous chunk
            {
                int u0 = tid, u1 = tid + 256;
                *((uint4*)&ws[(u0 >> 3) * WPITCH + (u0 & 7) * 8]) = w0;
                *((uint4*)&ws[(u1 >> 3) * WPITCH + (u1 & 7) * 8]) = w1;
            }
            __syncthreads();
            if (c + 1 < NCHUNKS) {  // prefetch next chunk while computing
                int u0 = tid, u1 = tid + 256;
                const __nv_bfloat16* wb = g_wbf + (size_t)(c + 1) * NCHUNK * DDIM;
                w0 = *((const uint4*)(wb + (u0 >> 3) * DDIM) + (u0 & 7));
                w1 = *((const uint4*)(wb + (u1 >> 3) * DDIM) + (u1 & 7));
            }

            // ---- 16x64x64 per warp: 32 HMMAs ----
            float acc[8][4];
            #pragma unroll
            for (int nt = 0; nt < 8; ++nt) {
                acc[nt][0] = acc[nt][1] = acc[nt][2] = acc[nt][3] = 0.f;
            }
            #pragma unroll
            for (int k = 0; k < 4; ++k) {
                uint32_t bfr[16];
                #pragma unroll
                for (int ng = 0; ng < 4; ++ng) {
                    const __nv_bfloat16* bp =
                        &ws[(ng * 16 + (lane & 15)) * WPITCH + k * 16 + (lane >> 4) * 8];
                    ldsm_x4(bfr[ng * 4], bfr[ng * 4 + 1], bfr[ng * 4 + 2], bfr[ng * 4 + 3], bp);
                }
                #pragma unroll
                for (int nt = 0; nt < 8; ++nt) {
                    int ng = nt >> 1, sub = nt & 1;
                    mma_bf16(acc[nt], afr[k], bfr[ng * 4 + sub], bfr[ng * 4 + 2 + sub]);
                }
            }

            // ---- fused epilogue: max over 32 cols (one p), sum over 16 rows ----
            // frag layout: acc[nt][0..1] row g cols 2c,2c+1 ; [2..3] row g+8
            #pragma unroll
            for (int pg = 0; pg < 2; ++pg) {
                float m0 = -3.4e38f, m1 = -3.4e38f;
                #pragma unroll
                for (int q = 0; q < 4; ++q) {
                    float* a = acc[pg * 4 + q];
                    m0 = fmaxf(m0, fmaxf(a[0], a[1]));
                    m1 = fmaxf(m1, fmaxf(a[2], a[3]));
                }
                // max across the 4 lanes of the quad -> max over all 32 cols
                m0 = fmaxf(m0, __shfl_xor_sync(0xffffffffu, m0, 1));
                m0 = fmaxf(m0, __shfl_xor_sync(0xffffffffu, m0, 2));
                m1 = fmaxf(m1, __shfl_xor_sync(0xffffffffu, m1, 1));
                m1 = fmaxf(m1, __shfl_xor_sync(0xffffffffu, m1, 2));
                float s = m0 + m1;               // rows g and g+8
                s += __shfl_xor_sync(0xffffffffu, s, 4);
                s += __shfl_xor_sync(0xffffffffu, s, 8);
                s += __shfl_xor_sync(0xffffffffu, s, 16);  // sum of all 16 rows
                if (lane == 0) atomicAdd(&pooled[c * 2 + pg], s);
            }
        }
    }

    // ---- L2 normalize pooled[0..127] and emit ----
    __syncthreads();
    float v = 0.f, s2 = 0.f;
    if (tid < PDIM) { v = pooled[tid]; s2 = v * v; }
    #pragma unroll
    for (int o = 16; o > 0; o >>= 1) s2 += __shfl_xor_sync(0xffffffffu, s2, o);
    if (lane == 0) red[warp] = s2;
    __syncthreads();
    if (tid < PDIM) {
        float n2  = red[0] + red[1] + red[2] + red[3];
        float nrm = sqrtf(n2);
        out[(size_t)b * PDIM + tid] = v / fmaxf(nrm, 1e-12f);
    }
}

// ---------------- launch ----------------

extern "C" void kernel_launch(void* const* d_in, const int* in_sizes, int n_in,
                              void* d_out, int out_size) {
    const float* x     = (const float*)d_in[0];
    const float* w     = (const float*)d_in[1];
    const int*   index = (const int*)d_in[2];
    float* out = (float*)d_out;

    int nw = in_sizes[1];            // P*E*D = 262144
    int B  = in_sizes[2];            // 1024

    convw_kernel<<<(nw + 255) / 256, 256>>>(w, nw);
    scan_kernel<<<1, MAXB>>>(index, B);
    main_kernel<<<B, THREADS>>>(x, index, out);
}